// round 2
// baseline (speedup 1.0000x reference)
#include <cuda_runtime.h>
#include <stdint.h>

#define NB 4096
#define ND 1024
#define NF 32768
#define NC 128     // candidates kept per row (fast-score top-NC)
#define SELK 64    // exact top-k

#define BM 128
#define BN 128
#define BK 16

// Scratch (device globals: allocation-free per harness rules)
static __device__ float g_pre[(size_t)NB * NF];     // 512 MB: fast pre-activations
static __device__ float g_wdect[(size_t)NF * ND];   // 128 MB: W_dec transposed to [F, D]
static __device__ int   g_cand[NB * NC];            // candidate feature indices
static __device__ float g_vals[NB * SELK];
static __device__ int   g_idx[NB * SELK];

// ---------------------------------------------------------------------------
// W_dec [D, F] row-major  ->  g_wdect [F, D] row-major
// ---------------------------------------------------------------------------
__global__ void __launch_bounds__(256) transpose_kernel(const float* __restrict__ Wdec) {
    __shared__ float tile[32][33];
    const int f0 = blockIdx.x * 32;
    const int d0 = blockIdx.y * 32;
    const int tx = threadIdx.x;   // 0..31
    const int ty = threadIdx.y;   // 0..7
#pragma unroll
    for (int i = 0; i < 32; i += 8)
        tile[ty + i][tx] = Wdec[(size_t)(d0 + ty + i) * NF + (f0 + tx)];
    __syncthreads();
#pragma unroll
    for (int i = 0; i < 32; i += 8)
        g_wdect[(size_t)(f0 + ty + i) * ND + (d0 + tx)] = tile[tx][ty + i];
}

// ---------------------------------------------------------------------------
// FAST PASS: pre[b,f] = relu( dot(x[b,:]-b_dec, W_enc[f,:]) + b_enc[f] )
// fp32 SIMT GEMM: 128x128 tile, BK=16, 256 threads, 8x8 per thread.
// Only used for candidate selection; exact values recomputed later.
// ---------------------------------------------------------------------------
__global__ void __launch_bounds__(256, 2) gemm_relu_kernel(
    const float* __restrict__ X, const float* __restrict__ W,
    const float* __restrict__ benc, const float* __restrict__ bdec)
{
    __shared__ float As[BK][BM + 4];
    __shared__ float Bs[BK][BN + 4];

    const int tid  = threadIdx.x;
    const int brow = blockIdx.y * BM;
    const int fcol = blockIdx.x * BN;

    const int lr = tid >> 2;          // 0..63
    const int lc = (tid & 3) * 4;     // 0,4,8,12

    const int ty   = tid >> 4;        // 0..15
    const int tx   = tid & 15;        // 0..15
    const int rowA = ty * 8;
    const int colB = tx * 8;

    float acc[8][8];
#pragma unroll
    for (int i = 0; i < 8; ++i)
#pragma unroll
        for (int j = 0; j < 8; ++j) acc[i][j] = 0.f;

    for (int k0 = 0; k0 < ND; k0 += BK) {
        const float4 bd = *(const float4*)(bdec + k0 + lc);
#pragma unroll
        for (int rr = 0; rr < 2; ++rr) {
            const int r = lr + rr * 64;
            const float4 a = *(const float4*)(X + (size_t)(brow + r) * ND + k0 + lc);
            As[lc + 0][r] = a.x - bd.x;
            As[lc + 1][r] = a.y - bd.y;
            As[lc + 2][r] = a.z - bd.z;
            As[lc + 3][r] = a.w - bd.w;
            const float4 b = *(const float4*)(W + (size_t)(fcol + r) * ND + k0 + lc);
            Bs[lc + 0][r] = b.x;
            Bs[lc + 1][r] = b.y;
            Bs[lc + 2][r] = b.z;
            Bs[lc + 3][r] = b.w;
        }
        __syncthreads();
#pragma unroll
        for (int kk = 0; kk < BK; ++kk) {
            float a[8], b[8];
            *(float4*)(a)     = *(const float4*)&As[kk][rowA];
            *(float4*)(a + 4) = *(const float4*)&As[kk][rowA + 4];
            *(float4*)(b)     = *(const float4*)&Bs[kk][colB];
            *(float4*)(b + 4) = *(const float4*)&Bs[kk][colB + 4];
#pragma unroll
            for (int i = 0; i < 8; ++i)
#pragma unroll
                for (int j = 0; j < 8; ++j)
                    acc[i][j] = fmaf(a[i], b[j], acc[i][j]);
        }
        __syncthreads();
    }

    float bb[8];
    *(float4*)(bb)     = *(const float4*)(benc + fcol + colB);
    *(float4*)(bb + 4) = *(const float4*)(benc + fcol + colB + 4);
#pragma unroll
    for (int i = 0; i < 8; ++i) {
        float* outp = g_pre + (size_t)(brow + rowA + i) * NF + fcol + colB;
        float o[8];
#pragma unroll
        for (int j = 0; j < 8; ++j) {
            const float v = acc[i][j] + bb[j];
            o[j] = v > 0.f ? v : 0.f;
        }
        *(float4*)(outp)     = *(const float4*)(o);
        *(float4*)(outp + 4) = *(const float4*)(o + 4);
    }
}

// ---------------------------------------------------------------------------
// Per-row top-NC CANDIDATE selection via 4-pass byte radix select on float
// bits (valid total order: all fast scores are >= 0 after ReLU).
// Only indices are kept; exact values are recomputed by refine_kernel.
// ---------------------------------------------------------------------------
__global__ void __launch_bounds__(256) topk_kernel() {
    const int row = blockIdx.x;
    const float* __restrict__ pre = g_pre + (size_t)row * NF;
    const int tid = threadIdx.x;

    __shared__ unsigned hist[256];
    __shared__ unsigned s_prefix, s_need, s_flag;
    __shared__ unsigned s_cnt, s_eqcnt;
    __shared__ int   eqbuf[256];
    __shared__ int   cand[NC];

    unsigned prefix = 0;
    unsigned need = NC;
    bool zerocase = false;

    // ---- pass 0 (top byte), with a 1.0f floor to cut atomic contention ----
    unsigned floor_bits = 0x3F800000u;  // 1.0f
    for (int attempt = 0; attempt < 2; ++attempt) {
        hist[tid] = 0u;
        __syncthreads();
        for (int j = tid; j < NF; j += 256) {
            const unsigned bits = __float_as_uint(pre[j]);
            if (bits > floor_bits) atomicAdd(&hist[bits >> 24], 1u);
        }
        __syncthreads();
        if (tid == 0) {
            unsigned total = 0;
            for (int b = 0; b < 256; ++b) total += hist[b];
            if (total < NC) {
                if (attempt == 0) {
                    s_flag = 1u;                        // retry without floor
                } else {
                    s_flag = 2u;                        // threshold is exactly 0
                    s_prefix = 0u;
                    s_need = NC - total;
                }
            } else {
                unsigned cum = 0; int sel = 255;
                for (int b = 255; b >= 0; --b) {
                    const unsigned h = hist[b];
                    if (cum + h >= NC) { sel = b; break; }
                    cum += h;
                }
                s_flag = 0u;
                s_prefix = (unsigned)sel;
                s_need = NC - cum;
            }
        }
        __syncthreads();
        const unsigned flag = s_flag;
        prefix = s_prefix;
        need = s_need;
        __syncthreads();
        if (flag == 0u) break;
        if (flag == 2u) { zerocase = true; break; }
        floor_bits = 0u;  // retry pass 0 counting all nonzero values
    }

    if (!zerocase) {
        // ---- passes 1..3 (refine byte by byte, full predicate, no floor) ---
        for (int pass = 1; pass < 4; ++pass) {
            const int shift = 24 - pass * 8;
            hist[tid] = 0u;
            __syncthreads();
            for (int j = tid; j < NF; j += 256) {
                const unsigned bits = __float_as_uint(pre[j]);
                if ((bits >> (shift + 8)) == prefix)
                    atomicAdd(&hist[(bits >> shift) & 255u], 1u);
            }
            __syncthreads();
            if (tid == 0) {
                unsigned cum = 0; int sel = 0;
                for (int b = 255; b >= 0; --b) {
                    const unsigned h = hist[b];
                    if (cum + h >= need) { sel = b; break; }
                    cum += h;
                }
                s_prefix = (prefix << 8) | (unsigned)sel;
                s_need = need - cum;
            }
            __syncthreads();
            prefix = s_prefix;
            need = s_need;
            __syncthreads();
        }
    }
    // prefix = fp32 bit pattern of the NC-th largest fast score;
    // need = how many values equal to it complete the candidate set.

    if (tid == 0) { s_cnt = 0u; s_eqcnt = 0u; }
    __syncthreads();
    for (int j = tid; j < NF; j += 256) {
        const unsigned bits = __float_as_uint(pre[j]);
        if (bits > prefix) {
            const unsigned p = atomicAdd(&s_cnt, 1u);
            if (p < NC) cand[p] = j;
        } else if (bits == prefix) {
            const unsigned q = atomicAdd(&s_eqcnt, 1u);
            if (q < 256u) eqbuf[q] = j;
        }
    }
    __syncthreads();
    if (tid == 0) {
        const int g = (int)s_cnt;   // == NC - need (exact by radix construction)
        const int m = (int)(s_eqcnt < 256u ? s_eqcnt : 256u);
        const int take = (int)need;
        // choose the `take` LOWEST tie indices (jax top_k stable tie-break):
        // partial selection over eqbuf (m is tiny except in the all-zero case)
        for (int i = 0; i < take && i < m; ++i) {
            int best = i;
            for (int a = i + 1; a < m; ++a)
                if (eqbuf[a] < eqbuf[best]) best = a;
            const int t = eqbuf[i]; eqbuf[i] = eqbuf[best]; eqbuf[best] = t;
            cand[g + i] = eqbuf[i];
        }
    }
    __syncthreads();
    if (tid < NC) g_cand[row * NC + tid] = cand[tid];
}

// ---------------------------------------------------------------------------
// EXACT refinement: recompute the NC candidate pre-activations with
// Neumaier-compensated fp32 (+ exact FMA product-error term) -> ~1e-9 abs
// error, then rank-select the true top-SELK (value desc, index asc).
// ---------------------------------------------------------------------------
__global__ void __launch_bounds__(256) refine_kernel(
    const float* __restrict__ X, const float* __restrict__ W,
    const float* __restrict__ benc, const float* __restrict__ bdec)
{
    const int row = blockIdx.x;
    const int tid = threadIdx.x;
    const int warp = tid >> 5;
    const int lane = tid & 31;

    __shared__ float  xs[ND];
    __shared__ double dv[NC];
    __shared__ int    di[NC];

    for (int j = tid; j < ND; j += 256)
        xs[j] = X[(size_t)row * ND + j] - bdec[j];
    if (tid < NC) di[tid] = g_cand[row * NC + tid];
    __syncthreads();

    for (int c = warp; c < NC; c += 8) {
        const int f = di[c];
        const float* __restrict__ w = W + (size_t)f * ND;
        float s = 0.f, cc = 0.f, es = 0.f;
#pragma unroll 4
        for (int j = lane; j < ND; j += 32) {
            const float a = xs[j];
            const float b = w[j];
            const float p = a * b;
            const float e = fmaf(a, b, -p);        // exact product error
            // Neumaier add of p into (s, cc)
            const float t = s + p;
            cc += (fabsf(s) >= fabsf(p)) ? ((s - t) + p) : ((p - t) + s);
            s = t;
            es += e;
        }
        double tot = (double)s + (double)cc + (double)es;
#pragma unroll
        for (int m = 16; m > 0; m >>= 1)
            tot += __shfl_xor_sync(0xffffffffu, tot, m);
        if (lane == 0) {
            tot += (double)benc[f];
            dv[c] = tot > 0.0 ? tot : 0.0;          // relu
        }
    }
    __syncthreads();

    if (tid < NC) {
        const double v = dv[tid];
        const int   ix = di[tid];
        int rank = 0;
#pragma unroll 8
        for (int j = 0; j < NC; ++j) {
            const double vj = dv[j];
            const int    ij = di[j];
            rank += (vj > v) || (vj == v && ij < ix);
        }
        if (rank < SELK) {
            g_vals[row * SELK + rank] = (float)v;
            g_idx [row * SELK + rank] = ix;
        }
    }
}

// ---------------------------------------------------------------------------
// x_hat[b,:] = b_dec + sum_k vals[b,k] * W_dec^T[idx[b,k], :]
// One CTA per row; contiguous 4 KB gathers from the transposed decoder.
// ---------------------------------------------------------------------------
__global__ void __launch_bounds__(256) decode_kernel(const float* __restrict__ bdec,
                                                     float* __restrict__ out) {
    const int row = blockIdx.x;
    __shared__ float sv[SELK];
    __shared__ int   si[SELK];
    if (threadIdx.x < SELK) {
        sv[threadIdx.x] = g_vals[row * SELK + threadIdx.x];
        si[threadIdx.x] = g_idx [row * SELK + threadIdx.x];
    }
    __syncthreads();
    const int d = threadIdx.x * 4;
    float4 acc = *(const float4*)(bdec + d);
#pragma unroll 8
    for (int k = 0; k < SELK; ++k) {
        const float v = sv[k];
        const float4 w = *(const float4*)(g_wdect + (size_t)si[k] * ND + d);
        acc.x = fmaf(v, w.x, acc.x);
        acc.y = fmaf(v, w.y, acc.y);
        acc.z = fmaf(v, w.z, acc.z);
        acc.w = fmaf(v, w.w, acc.w);
    }
    *(float4*)(out + (size_t)row * ND + d) = acc;
}

// ---------------------------------------------------------------------------
extern "C" void kernel_launch(void* const* d_in, const int* in_sizes, int n_in,
                              void* d_out, int out_size) {
    const float* x    = (const float*)d_in[0];   // [4096, 1024]
    const float* Wenc = (const float*)d_in[1];   // [32768, 1024]
    const float* benc = (const float*)d_in[2];   // [32768]
    const float* Wdec = (const float*)d_in[3];   // [1024, 32768]
    const float* bdec = (const float*)d_in[4];   // [1024]
    float* out = (float*)d_out;                  // [4096, 1024]

    transpose_kernel<<<dim3(NF / 32, ND / 32), dim3(32, 8)>>>(Wdec);
    gemm_relu_kernel<<<dim3(NF / BN, NB / BM), 256>>>(x, Wenc, benc, bdec);
    topk_kernel<<<NB, 256>>>();
    refine_kernel<<<NB, 256>>>(x, Wenc, benc, bdec);
    decode_kernel<<<NB, 256>>>(bdec, out);
}

// round 4
// speedup vs baseline: 2.7679x; 2.7679x over previous
#include <cuda_runtime.h>
#include <cuda_bf16.h>
#include <stdint.h>

#define NB 4096
#define ND 1024
#define NF 32768
#define NC 128     // candidates kept per row
#define SELK 64    // exact top-k

// ---- GEMM tiling (HMMA mma.sync path; compute_103-safe) ----
#define GBM 128
#define GBN 128
#define GBK 64
#define KITERS (ND / GBK)          // 16
#define OFF_A(s)  ((s) * 16384)    // A stages: 2 x 16KB
#define OFF_B(s)  (32768 + (s) * 16384)
#define OFF_BIAS  65536            // 128 floats
#define GEMM_SMEM 66048
#define EPI_STRIDE 68              // u32 stride, conflict-free epilogue staging

// ---- device scratch (allocation-free) ----
static __device__ __align__(16) __nv_bfloat16 g_abf[(size_t)NB * ND];
static __device__ __align__(16) __nv_bfloat16 g_wbf[(size_t)NF * ND];
static __device__ __align__(16) __nv_bfloat16 g_prebf[(size_t)NB * NF];
static __device__ float g_wdect[(size_t)NF * ND];
static __device__ int   g_cand[NB * NC];
static __device__ float g_vals[NB * SELK];
static __device__ int   g_idx[NB * SELK];

// ============================ PTX helpers ===================================
__device__ __forceinline__ uint32_t smem_u32(const void* p) {
    uint32_t a;
    asm("{ .reg .u64 t; cvta.to.shared.u64 t, %1; cvt.u32.u64 %0, t; }"
        : "=r"(a) : "l"(p));
    return a;
}
__device__ __forceinline__ uint32_t pack_bf16x2(float lo, float hi) {
    uint32_t r;
    asm("cvt.rn.bf16x2.f32 %0, %2, %1;" : "=r"(r) : "f"(lo), "f"(hi));
    return r;
}
__device__ __forceinline__ void cp_async16(uint32_t dst, const void* src) {
    asm volatile("cp.async.cg.shared.global [%0], [%1], 16;"
                 :: "r"(dst), "l"(src) : "memory");
}
__device__ __forceinline__ void cp_commit() {
    asm volatile("cp.async.commit_group;" ::: "memory");
}
template <int N>
__device__ __forceinline__ void cp_wait() {
    asm volatile("cp.async.wait_group %0;" :: "n"(N) : "memory");
}
__device__ __forceinline__ void ldmatrix_x4(uint32_t& r0, uint32_t& r1,
                                            uint32_t& r2, uint32_t& r3, uint32_t a) {
    asm volatile("ldmatrix.sync.aligned.m8n8.x4.shared.b16 {%0,%1,%2,%3}, [%4];"
                 : "=r"(r0), "=r"(r1), "=r"(r2), "=r"(r3) : "r"(a));
}
__device__ __forceinline__ void mma_bf16(float* c, const uint32_t* a, const uint32_t* b) {
    asm volatile(
        "mma.sync.aligned.m16n8k16.row.col.f32.bf16.bf16.f32 "
        "{%0,%1,%2,%3}, {%4,%5,%6,%7}, {%8,%9}, {%0,%1,%2,%3};"
        : "+f"(c[0]), "+f"(c[1]), "+f"(c[2]), "+f"(c[3])
        : "r"(a[0]), "r"(a[1]), "r"(a[2]), "r"(a[3]), "r"(b[0]), "r"(b[1]));
}

// ======================== conversion kernels ================================
__global__ void __launch_bounds__(256) convx_kernel(const float* __restrict__ X,
                                                    const float* __restrict__ bdec) {
    const int n4 = NB * ND / 4;
    for (int i = blockIdx.x * 256 + threadIdx.x; i < n4; i += gridDim.x * 256) {
        const float4 v = ((const float4*)X)[i];
        const float4 bd = ((const float4*)bdec)[i & (ND / 4 - 1)];
        uint2 o;
        o.x = pack_bf16x2(v.x - bd.x, v.y - bd.y);
        o.y = pack_bf16x2(v.z - bd.z, v.w - bd.w);
        ((uint2*)g_abf)[i] = o;
    }
}
__global__ void __launch_bounds__(256) convw_kernel(const float* __restrict__ W) {
    const int n4 = NF * ND / 4;
    for (int i = blockIdx.x * 256 + threadIdx.x; i < n4; i += gridDim.x * 256) {
        const float4 v = ((const float4*)W)[i];
        uint2 o;
        o.x = pack_bf16x2(v.x, v.y);
        o.y = pack_bf16x2(v.z, v.w);
        ((uint2*)g_wbf)[i] = o;
    }
}

// ========================= W_dec transpose ==================================
__global__ void __launch_bounds__(256) transpose_kernel(const float* __restrict__ Wdec) {
    __shared__ float tile[32][33];
    const int f0 = blockIdx.x * 32;
    const int d0 = blockIdx.y * 32;
    const int tx = threadIdx.x, ty = threadIdx.y;
#pragma unroll
    for (int i = 0; i < 32; i += 8)
        tile[ty + i][tx] = Wdec[(size_t)(d0 + ty + i) * NF + (f0 + tx)];
    __syncthreads();
#pragma unroll
    for (int i = 0; i < 32; i += 8)
        g_wdect[(size_t)(f0 + ty + i) * ND + (d0 + tx)] = tile[tx][ty + i];
}

// ================ bf16 HMMA fast-score GEMM (mma.sync path) =================
// smem rows are 128B (64 bf16); 16B chunk c of row r stored at chunk c^(r&7).
__device__ __forceinline__ uint32_t swz(uint32_t base, int row, int c) {
    return base + row * 128 + 16 * (c ^ (row & 7));
}

__global__ void __launch_bounds__(256) gemm_bf16_kernel(const float* __restrict__ benc) {
    extern __shared__ char smem[];
    const uint32_t sbase = smem_u32(smem);
    const int tid = threadIdx.x;
    const int wid = tid >> 5;
    const int lane = tid & 31;
    const int warp_m = wid & 1;    // 2 warps over M (64 rows each)
    const int warp_n = wid >> 1;   // 4 warps over N (32 cols each)
    const int fcol = blockIdx.x * GBN;
    const int brow = blockIdx.y * GBM;

    float* sbias = (float*)(smem + OFF_BIAS);
    for (int i = tid; i < GBN; i += 256) sbias[i] = benc[fcol + i];

    const __nv_bfloat16* __restrict__ Ag = g_abf + (size_t)brow * ND;
    const __nv_bfloat16* __restrict__ Bg = g_wbf + (size_t)fcol * ND;

    // per-thread load slots: 4 A chunks + 4 B chunks per stage
    const int lrow = tid >> 3;         // 0..31  (+32 per slot)
    const int lc = tid & 7;            // chunk 0..7

    // prefetch stage 0
    {
        const int kb = 0;
#pragma unroll
        for (int s = 0; s < 4; ++s) {
            const int row = lrow + s * 32;
            cp_async16(swz(sbase + OFF_A(0), row, lc), Ag + (size_t)row * ND + kb + lc * 8);
            cp_async16(swz(sbase + OFF_B(0), row, lc), Bg + (size_t)row * ND + kb + lc * 8);
        }
        cp_commit();
    }

    float acc[4][4][4];
#pragma unroll
    for (int i = 0; i < 4; ++i)
#pragma unroll
        for (int j = 0; j < 4; ++j)
#pragma unroll
            for (int r = 0; r < 4; ++r) acc[i][j][r] = 0.f;

    for (int it = 0; it < KITERS; ++it) {
        const int buf = it & 1;
        if (it + 1 < KITERS) {
            const int kb = (it + 1) * GBK;
            const int nbuf = (it + 1) & 1;
#pragma unroll
            for (int s = 0; s < 4; ++s) {
                const int row = lrow + s * 32;
                cp_async16(swz(sbase + OFF_A(nbuf), row, lc), Ag + (size_t)row * ND + kb + lc * 8);
                cp_async16(swz(sbase + OFF_B(nbuf), row, lc), Bg + (size_t)row * ND + kb + lc * 8);
            }
            cp_commit();
            cp_wait<1>();
        } else {
            cp_wait<0>();
        }
        __syncthreads();

        const uint32_t sA = sbase + OFF_A(buf);
        const uint32_t sB = sbase + OFF_B(buf);
#pragma unroll
        for (int ks = 0; ks < 4; ++ks) {
            const int c0 = ks * 2;
            uint32_t af[4][4], bf[2][4];
#pragma unroll
            for (int i = 0; i < 4; ++i) {
                const int row = warp_m * 64 + i * 16 + (lane & 15);
                const int cc = c0 + (lane >> 4);
                ldmatrix_x4(af[i][0], af[i][1], af[i][2], af[i][3], swz(sA, row, cc));
            }
#pragma unroll
            for (int j2 = 0; j2 < 2; ++j2) {
                const int row = warp_n * 32 + j2 * 16 + (lane & 7) + ((lane >> 4) << 3);
                const int cc = c0 + ((lane >> 3) & 1);
                ldmatrix_x4(bf[j2][0], bf[j2][1], bf[j2][2], bf[j2][3], swz(sB, row, cc));
            }
#pragma unroll
            for (int i = 0; i < 4; ++i)
#pragma unroll
                for (int j = 0; j < 4; ++j)
                    mma_bf16(acc[i][j], af[i], &bf[j >> 1][(j & 1) * 2]);
        }
        __syncthreads();
    }

    // epilogue: +bias, relu, bf16 pack -> staged smem -> coalesced gmem
    uint32_t* epi = (uint32_t*)smem;
    const int g = lane >> 2, tig = lane & 3;
#pragma unroll
    for (int i = 0; i < 4; ++i) {
#pragma unroll
        for (int j = 0; j < 4; ++j) {
            const int col = warp_n * 32 + j * 8 + 2 * tig;
            const float b0 = sbias[col], b1 = sbias[col + 1];
            const int cp = col >> 1;
            float v0 = acc[i][j][0] + b0, v1 = acc[i][j][1] + b1;
            float v2 = acc[i][j][2] + b0, v3 = acc[i][j][3] + b1;
            v0 = v0 > 0.f ? v0 : 0.f; v1 = v1 > 0.f ? v1 : 0.f;
            v2 = v2 > 0.f ? v2 : 0.f; v3 = v3 > 0.f ? v3 : 0.f;
            const int row0 = warp_m * 64 + i * 16 + g;
            epi[(row0)     * EPI_STRIDE + cp] = pack_bf16x2(v0, v1);
            epi[(row0 + 8) * EPI_STRIDE + cp] = pack_bf16x2(v2, v3);
        }
    }
    __syncthreads();
#pragma unroll
    for (int s = 0; s < 8; ++s) {
        const int idx = tid + s * 256;          // 0..2047
        const int row = idx >> 4, q = idx & 15;
        uint4 v;
        v.x = epi[row * EPI_STRIDE + q * 4 + 0];
        v.y = epi[row * EPI_STRIDE + q * 4 + 1];
        v.z = epi[row * EPI_STRIDE + q * 4 + 2];
        v.w = epi[row * EPI_STRIDE + q * 4 + 3];
        *(uint4*)(g_prebf + (size_t)(brow + row) * NF + fcol + q * 8) = v;
    }
}

// =============== per-row top-NC candidates: 2-pass bf16 radix ===============
__global__ void __launch_bounds__(256) topk_kernel() {
    const int row = blockIdx.x;
    const uint4* __restrict__ p4 = (const uint4*)(g_prebf + (size_t)row * NF);
    const int tid = threadIdx.x;

    __shared__ unsigned hist[256];
    __shared__ unsigned s_prefix, s_need, s_flag, s_cnt, s_eqcnt;
    __shared__ int eqbuf[256];
    __shared__ int cand[NC];

    unsigned prefix = 0, need = NC;
    bool zerocase = false;

    unsigned floorb = 0x3F80u;   // 1.0f in bf16
    for (int attempt = 0; attempt < 2; ++attempt) {
        hist[tid] = 0u;
        __syncthreads();
        for (int i = tid; i < NF / 8; i += 256) {
            const uint4 v = p4[i];
            const unsigned w[4] = {v.x, v.y, v.z, v.w};
#pragma unroll
            for (int q = 0; q < 4; ++q) {
                const unsigned k0 = w[q] & 0xFFFFu, k1 = w[q] >> 16;
                if (k0 > floorb) atomicAdd(&hist[k0 >> 8], 1u);
                if (k1 > floorb) atomicAdd(&hist[k1 >> 8], 1u);
            }
        }
        __syncthreads();
        if (tid == 0) {
            unsigned total = 0;
            for (int b = 0; b < 256; ++b) total += hist[b];
            if (total < NC) {
                if (attempt == 0) s_flag = 1u;
                else { s_flag = 2u; s_prefix = 0u; s_need = NC - total; }
            } else {
                unsigned cum = 0; int sel = 255;
                for (int b = 255; b >= 0; --b) {
                    const unsigned h = hist[b];
                    if (cum + h >= NC) { sel = b; break; }
                    cum += h;
                }
                s_flag = 0u; s_prefix = (unsigned)sel; s_need = NC - cum;
            }
        }
        __syncthreads();
        const unsigned flag = s_flag;
        prefix = s_prefix; need = s_need;
        __syncthreads();
        if (flag == 0u) break;
        if (flag == 2u) { zerocase = true; break; }
        floorb = 0u;
    }

    if (!zerocase) {
        hist[tid] = 0u;
        __syncthreads();
        for (int i = tid; i < NF / 8; i += 256) {
            const uint4 v = p4[i];
            const unsigned w[4] = {v.x, v.y, v.z, v.w};
#pragma unroll
            for (int q = 0; q < 4; ++q) {
                const unsigned k0 = w[q] & 0xFFFFu, k1 = w[q] >> 16;
                if ((k0 >> 8) == prefix) atomicAdd(&hist[k0 & 255u], 1u);
                if ((k1 >> 8) == prefix) atomicAdd(&hist[k1 & 255u], 1u);
            }
        }
        __syncthreads();
        if (tid == 0) {
            unsigned cum = 0; int sel = 0;
            for (int b = 255; b >= 0; --b) {
                const unsigned h = hist[b];
                if (cum + h >= need) { sel = b; break; }
                cum += h;
            }
            s_prefix = (prefix << 8) | (unsigned)sel;
            s_need = need - cum;
        }
        __syncthreads();
        prefix = s_prefix; need = s_need;
        __syncthreads();
    }

    if (tid == 0) { s_cnt = 0u; s_eqcnt = 0u; }
    __syncthreads();
    for (int i = tid; i < NF / 8; i += 256) {
        const uint4 v = p4[i];
        const unsigned w[4] = {v.x, v.y, v.z, v.w};
#pragma unroll
        for (int q = 0; q < 4; ++q) {
#pragma unroll
            for (int h = 0; h < 2; ++h) {
                const unsigned k = h ? (w[q] >> 16) : (w[q] & 0xFFFFu);
                const int j = i * 8 + q * 2 + h;
                if (k > prefix) {
                    const unsigned p = atomicAdd(&s_cnt, 1u);
                    if (p < NC) cand[p] = j;
                } else if (k == prefix) {
                    const unsigned e = atomicAdd(&s_eqcnt, 1u);
                    if (e < 256u) eqbuf[e] = j;
                }
            }
        }
    }
    __syncthreads();
    if (tid == 0) {
        const int g = (int)s_cnt;            // == NC - need
        const int m = (int)(s_eqcnt < 256u ? s_eqcnt : 256u);
        const int take = (int)need;
        for (int i = 0; i < take; ++i) {
            if (i < m) {
                int best = i;
                for (int a = i + 1; a < m; ++a)
                    if (eqbuf[a] < eqbuf[best]) best = a;
                const int t = eqbuf[i]; eqbuf[i] = eqbuf[best]; eqbuf[best] = t;
                if (g + i < NC) cand[g + i] = eqbuf[i];
            } else {
                if (g + i < NC) cand[g + i] = NF - 1 - i;  // degenerate filler
            }
        }
    }
    __syncthreads();
    if (tid < NC) g_cand[row * NC + tid] = cand[tid];
}

// ================= exact refinement (Neumaier, unchanged math) ==============
__device__ __forceinline__ void neum(float& s, float& c, float& e, float a, float b) {
    const float p = a * b;
    e += fmaf(a, b, -p);
    const float t = s + p;
    c += (fabsf(s) >= fabsf(p)) ? ((s - t) + p) : ((p - t) + s);
    s = t;
}

__global__ void __launch_bounds__(512) refine_kernel(
    const float* __restrict__ X, const float* __restrict__ W,
    const float* __restrict__ benc, const float* __restrict__ bdec)
{
    const int row = blockIdx.x;
    const int tid = threadIdx.x;
    const int warp = tid >> 5;
    const int lane = tid & 31;

    __shared__ float  xs[ND];
    __shared__ double dv[NC];
    __shared__ int    di[NC];

    for (int j = tid; j < ND; j += 512)
        xs[j] = X[(size_t)row * ND + j] - bdec[j];
    if (tid < NC) di[tid] = g_cand[row * NC + tid];
    __syncthreads();

    for (int sweep = 0; sweep < 4; ++sweep) {
        const int c0 = sweep * 32 + warp * 2;
        const int f0 = di[c0], f1 = di[c0 + 1];
        const float4* __restrict__ w0 = (const float4*)(W + (size_t)f0 * ND);
        const float4* __restrict__ w1 = (const float4*)(W + (size_t)f1 * ND);
        float s0 = 0.f, cc0 = 0.f, e0 = 0.f;
        float s1 = 0.f, cc1 = 0.f, e1 = 0.f;
#pragma unroll
        for (int t = 0; t < 8; ++t) {
            const int j4 = t * 32 + lane;
            const float4 xv = *(const float4*)&xs[j4 * 4];
            const float4 a = __ldg(w0 + j4);
            const float4 b = __ldg(w1 + j4);
            neum(s0, cc0, e0, xv.x, a.x); neum(s1, cc1, e1, xv.x, b.x);
            neum(s0, cc0, e0, xv.y, a.y); neum(s1, cc1, e1, xv.y, b.y);
            neum(s0, cc0, e0, xv.z, a.z); neum(s1, cc1, e1, xv.z, b.z);
            neum(s0, cc0, e0, xv.w, a.w); neum(s1, cc1, e1, xv.w, b.w);
        }
        double t0 = (double)s0 + (double)cc0 + (double)e0;
        double t1 = (double)s1 + (double)cc1 + (double)e1;
#pragma unroll
        for (int m = 16; m > 0; m >>= 1) {
            t0 += __shfl_xor_sync(0xffffffffu, t0, m);
            t1 += __shfl_xor_sync(0xffffffffu, t1, m);
        }
        if (lane == 0) {
            t0 += (double)benc[f0];
            t1 += (double)benc[f1];
            dv[c0]     = t0 > 0.0 ? t0 : 0.0;
            dv[c0 + 1] = t1 > 0.0 ? t1 : 0.0;
        }
    }
    __syncthreads();

    if (tid < NC) {
        const double v = dv[tid];
        const int   ix = di[tid];
        int rank = 0;
#pragma unroll 8
        for (int j = 0; j < NC; ++j) {
            const double vj = dv[j];
            const int    ij = di[j];
            rank += (vj > v) || (vj == v && ij < ix);
        }
        if (rank < SELK) {
            g_vals[row * SELK + rank] = (float)v;
            g_idx [row * SELK + rank] = ix;
        }
    }
}

// =============================== decode =====================================
__global__ void __launch_bounds__(256) decode_kernel(const float* __restrict__ bdec,
                                                     float* __restrict__ out) {
    const int row = blockIdx.x;
    __shared__ float sv[SELK];
    __shared__ int   si[SELK];
    if (threadIdx.x < SELK) {
        sv[threadIdx.x] = g_vals[row * SELK + threadIdx.x];
        si[threadIdx.x] = g_idx [row * SELK + threadIdx.x];
    }
    __syncthreads();
    const int d = threadIdx.x * 4;
    float4 acc = *(const float4*)(bdec + d);
#pragma unroll 8
    for (int k = 0; k < SELK; ++k) {
        const float v = sv[k];
        const float4 w = *(const float4*)(g_wdect + (size_t)si[k] * ND + d);
        acc.x = fmaf(v, w.x, acc.x);
        acc.y = fmaf(v, w.y, acc.y);
        acc.z = fmaf(v, w.z, acc.z);
        acc.w = fmaf(v, w.w, acc.w);
    }
    *(float4*)(out + (size_t)row * ND + d) = acc;
}

// ============================================================================
extern "C" void kernel_launch(void* const* d_in, const int* in_sizes, int n_in,
                              void* d_out, int out_size) {
    const float* x    = (const float*)d_in[0];   // [4096, 1024]
    const float* Wenc = (const float*)d_in[1];   // [32768, 1024]
    const float* benc = (const float*)d_in[2];   // [32768]
    const float* Wdec = (const float*)d_in[3];   // [1024, 32768]
    const float* bdec = (const float*)d_in[4];   // [1024]
    float* out = (float*)d_out;                  // [4096, 1024]

    cudaFuncSetAttribute(gemm_bf16_kernel,
                         cudaFuncAttributeMaxDynamicSharedMemorySize, GEMM_SMEM);

    convx_kernel<<<256, 256>>>(x, bdec);
    convw_kernel<<<1024, 256>>>(Wenc);
    transpose_kernel<<<dim3(NF / 32, ND / 32), dim3(32, 8)>>>(Wdec);
    gemm_bf16_kernel<<<dim3(NF / GBN, NB / GBM), 256, GEMM_SMEM>>>(benc);
    topk_kernel<<<NB, 256>>>();
    refine_kernel<<<NB, 512>>>(x, Wenc, benc, bdec);
    decode_kernel<<<NB, 256>>>(bdec, out);
}

// round 5
// speedup vs baseline: 4.2700x; 1.5427x over previous
#include <cuda_runtime.h>
#include <cuda_bf16.h>
#include <stdint.h>

#define NB 4096
#define ND 1024
#define NF 32768
#define NC 128     // candidates kept per row
#define SELK 64    // exact top-k

// ---- GEMM tiling (HMMA mma.sync path; compute_103-safe) ----
#define GBM 128
#define GBN 128
#define GBK 64
#define KITERS (ND / GBK)          // 16
#define NSTAGE 3
#define OFF_A(s)  ((s) * 16384)              // A stages: 3 x 16KB
#define OFF_B(s)  (49152 + (s) * 16384)      // B stages: 3 x 16KB
#define OFF_BIAS  98304                      // 128 floats
#define GEMM_SMEM 98816
#define EPI_STRIDE 68              // u32 stride, conflict-free epilogue staging

// ---- device scratch (allocation-free) ----
static __device__ __align__(16) __nv_bfloat16 g_abf[(size_t)NB * ND];
static __device__ __align__(16) __nv_bfloat16 g_wbf[(size_t)NF * ND];
static __device__ __align__(16) __nv_bfloat16 g_prebf[(size_t)NB * NF];
static __device__ float g_wdect[(size_t)NF * ND];
static __device__ int   g_cand[NB * NC];
static __device__ float g_vals[NB * SELK];
static __device__ int   g_idx[NB * SELK];

// ============================ PTX helpers ===================================
__device__ __forceinline__ uint32_t smem_u32(const void* p) {
    uint32_t a;
    asm("{ .reg .u64 t; cvta.to.shared.u64 t, %1; cvt.u32.u64 %0, t; }"
        : "=r"(a) : "l"(p));
    return a;
}
__device__ __forceinline__ uint32_t pack_bf16x2(float lo, float hi) {
    uint32_t r;
    asm("cvt.rn.bf16x2.f32 %0, %2, %1;" : "=r"(r) : "f"(lo), "f"(hi));
    return r;
}
__device__ __forceinline__ void cp_async16(uint32_t dst, const void* src) {
    asm volatile("cp.async.cg.shared.global [%0], [%1], 16;"
                 :: "r"(dst), "l"(src) : "memory");
}
__device__ __forceinline__ void cp_commit() {
    asm volatile("cp.async.commit_group;" ::: "memory");
}
template <int N>
__device__ __forceinline__ void cp_wait() {
    asm volatile("cp.async.wait_group %0;" :: "n"(N) : "memory");
}
__device__ __forceinline__ void ldmatrix_x4(uint32_t& r0, uint32_t& r1,
                                            uint32_t& r2, uint32_t& r3, uint32_t a) {
    asm volatile("ldmatrix.sync.aligned.m8n8.x4.shared.b16 {%0,%1,%2,%3}, [%4];"
                 : "=r"(r0), "=r"(r1), "=r"(r2), "=r"(r3) : "r"(a));
}
__device__ __forceinline__ void mma_bf16(float* c, const uint32_t* a, const uint32_t* b) {
    asm volatile(
        "mma.sync.aligned.m16n8k16.row.col.f32.bf16.bf16.f32 "
        "{%0,%1,%2,%3}, {%4,%5,%6,%7}, {%8,%9}, {%0,%1,%2,%3};"
        : "+f"(c[0]), "+f"(c[1]), "+f"(c[2]), "+f"(c[3])
        : "r"(a[0]), "r"(a[1]), "r"(a[2]), "r"(a[3]), "r"(b[0]), "r"(b[1]));
}

// ======================== conversion kernels ================================
__global__ void __launch_bounds__(256) convx_kernel(const float* __restrict__ X,
                                                    const float* __restrict__ bdec) {
    const int n4 = NB * ND / 4;
    for (int i = blockIdx.x * 256 + threadIdx.x; i < n4; i += gridDim.x * 256) {
        const float4 v = ((const float4*)X)[i];
        const float4 bd = ((const float4*)bdec)[i & (ND / 4 - 1)];
        uint2 o;
        o.x = pack_bf16x2(v.x - bd.x, v.y - bd.y);
        o.y = pack_bf16x2(v.z - bd.z, v.w - bd.w);
        ((uint2*)g_abf)[i] = o;
    }
}
__global__ void __launch_bounds__(256) convw_kernel(const float* __restrict__ W) {
    const int n4 = NF * ND / 4;
    for (int i = blockIdx.x * 256 + threadIdx.x; i < n4; i += gridDim.x * 256) {
        const float4 v = ((const float4*)W)[i];
        uint2 o;
        o.x = pack_bf16x2(v.x, v.y);
        o.y = pack_bf16x2(v.z, v.w);
        ((uint2*)g_wbf)[i] = o;
    }
}

// ========================= W_dec transpose ==================================
__global__ void __launch_bounds__(256) transpose_kernel(const float* __restrict__ Wdec) {
    __shared__ float tile[32][33];
    const int f0 = blockIdx.x * 32;
    const int d0 = blockIdx.y * 32;
    const int tx = threadIdx.x, ty = threadIdx.y;
#pragma unroll
    for (int i = 0; i < 32; i += 8)
        tile[ty + i][tx] = Wdec[(size_t)(d0 + ty + i) * NF + (f0 + tx)];
    __syncthreads();
#pragma unroll
    for (int i = 0; i < 32; i += 8)
        g_wdect[(size_t)(f0 + ty + i) * ND + (d0 + tx)] = tile[tx][ty + i];
}

// ================ bf16 HMMA fast-score GEMM (3-stage cp.async) ==============
// smem rows are 128B (64 bf16); 16B chunk c of row r stored at chunk c^(r&7).
__device__ __forceinline__ uint32_t swz(uint32_t base, int row, int c) {
    return base + row * 128 + 16 * (c ^ (row & 7));
}

__global__ void __launch_bounds__(256) gemm_bf16_kernel(const float* __restrict__ benc) {
    extern __shared__ char smem[];
    const uint32_t sbase = smem_u32(smem);
    const int tid = threadIdx.x;
    const int wid = tid >> 5;
    const int lane = tid & 31;
    const int warp_m = wid & 1;    // 2 warps over M (64 rows each)
    const int warp_n = wid >> 1;   // 4 warps over N (32 cols each)
    const int fcol = blockIdx.x * GBN;
    const int brow = blockIdx.y * GBM;

    float* sbias = (float*)(smem + OFF_BIAS);
    for (int i = tid; i < GBN; i += 256) sbias[i] = benc[fcol + i];

    const __nv_bfloat16* __restrict__ Ag = g_abf + (size_t)brow * ND;
    const __nv_bfloat16* __restrict__ Bg = g_wbf + (size_t)fcol * ND;

    const int lrow = tid >> 3;         // 0..31  (+32 per slot)
    const int lc = tid & 7;            // chunk 0..7

    // prefetch stages 0 and 1
#pragma unroll
    for (int st = 0; st < 2; ++st) {
        const int kb = st * GBK;
#pragma unroll
        for (int s = 0; s < 4; ++s) {
            const int row = lrow + s * 32;
            cp_async16(swz(sbase + OFF_A(st), row, lc), Ag + (size_t)row * ND + kb + lc * 8);
            cp_async16(swz(sbase + OFF_B(st), row, lc), Bg + (size_t)row * ND + kb + lc * 8);
        }
        cp_commit();
    }

    float acc[4][4][4];
#pragma unroll
    for (int i = 0; i < 4; ++i)
#pragma unroll
        for (int j = 0; j < 4; ++j)
#pragma unroll
            for (int r = 0; r < 4; ++r) acc[i][j][r] = 0.f;

    for (int it = 0; it < KITERS; ++it) {
        const int buf = it % NSTAGE;
        cp_wait<1>();          // stage `it` resident (1 younger group still in flight)
        __syncthreads();       // also guarantees compute of it-1 finished everywhere

        // issue stage it+2 into buffer (it+2)%3 (the one computed at it-1)
        if (it + 2 < KITERS) {
            const int kb = (it + 2) * GBK;
            const int nbuf = (it + 2) % NSTAGE;
#pragma unroll
            for (int s = 0; s < 4; ++s) {
                const int row = lrow + s * 32;
                cp_async16(swz(sbase + OFF_A(nbuf), row, lc), Ag + (size_t)row * ND + kb + lc * 8);
                cp_async16(swz(sbase + OFF_B(nbuf), row, lc), Bg + (size_t)row * ND + kb + lc * 8);
            }
        }
        cp_commit();           // commit (possibly empty) keeps group accounting uniform

        const uint32_t sA = sbase + OFF_A(buf);
        const uint32_t sB = sbase + OFF_B(buf);
#pragma unroll
        for (int ks = 0; ks < 4; ++ks) {
            const int c0 = ks * 2;
            uint32_t af[4][4], bf[2][4];
#pragma unroll
            for (int i = 0; i < 4; ++i) {
                const int row = warp_m * 64 + i * 16 + (lane & 15);
                const int cc = c0 + (lane >> 4);
                ldmatrix_x4(af[i][0], af[i][1], af[i][2], af[i][3], swz(sA, row, cc));
            }
#pragma unroll
            for (int j2 = 0; j2 < 2; ++j2) {
                const int row = warp_n * 32 + j2 * 16 + (lane & 7) + ((lane >> 4) << 3);
                const int cc = c0 + ((lane >> 3) & 1);
                ldmatrix_x4(bf[j2][0], bf[j2][1], bf[j2][2], bf[j2][3], swz(sB, row, cc));
            }
#pragma unroll
            for (int i = 0; i < 4; ++i)
#pragma unroll
                for (int j = 0; j < 4; ++j)
                    mma_bf16(acc[i][j], af[i], &bf[j >> 1][(j & 1) * 2]);
        }
    }
    __syncthreads();

    // epilogue: +bias, relu, bf16 pack -> staged smem -> coalesced gmem
    uint32_t* epi = (uint32_t*)smem;
    const int g = lane >> 2, tig = lane & 3;
#pragma unroll
    for (int i = 0; i < 4; ++i) {
#pragma unroll
        for (int j = 0; j < 4; ++j) {
            const int col = warp_n * 32 + j * 8 + 2 * tig;
            const float b0 = sbias[col], b1 = sbias[col + 1];
            const int cp = col >> 1;
            float v0 = acc[i][j][0] + b0, v1 = acc[i][j][1] + b1;
            float v2 = acc[i][j][2] + b0, v3 = acc[i][j][3] + b1;
            v0 = v0 > 0.f ? v0 : 0.f; v1 = v1 > 0.f ? v1 : 0.f;
            v2 = v2 > 0.f ? v2 : 0.f; v3 = v3 > 0.f ? v3 : 0.f;
            const int row0 = warp_m * 64 + i * 16 + g;
            epi[(row0)     * EPI_STRIDE + cp] = pack_bf16x2(v0, v1);
            epi[(row0 + 8) * EPI_STRIDE + cp] = pack_bf16x2(v2, v3);
        }
    }
    __syncthreads();
#pragma unroll
    for (int s = 0; s < 8; ++s) {
        const int idx = tid + s * 256;          // 0..2047
        const int row = idx >> 4, q = idx & 15;
        uint4 v;
        v.x = epi[row * EPI_STRIDE + q * 4 + 0];
        v.y = epi[row * EPI_STRIDE + q * 4 + 1];
        v.z = epi[row * EPI_STRIDE + q * 4 + 2];
        v.w = epi[row * EPI_STRIDE + q * 4 + 3];
        *(uint4*)(g_prebf + (size_t)(brow + row) * NF + fcol + q * 8) = v;
    }
}

// ====== per-row top-NC candidates: pass0 hist + fused pass1/compaction ======
#define EQCAP 6144

__global__ void __launch_bounds__(256) topk_kernel() {
    const int row = blockIdx.x;
    const uint4* __restrict__ p4 = (const uint4*)(g_prebf + (size_t)row * NF);
    const int tid = threadIdx.x;

    __shared__ unsigned hist[256];
    __shared__ unsigned s_prefix, s_need, s_flag, s_cnt, s_eqcnt, s_tiecnt;
    __shared__ int cand[NC];
    __shared__ int tiebuf[256];
    __shared__ unsigned eqbuf[EQCAP];   // (key16 << 16) | idx

    unsigned selhi = 0, need = NC;
    bool fallback_scan = false;         // zerocase or eq-overflow -> global re-scan
    unsigned prefix = 0;                // full 16-bit threshold key

    // ---- pass 0: high-byte histogram (floor 1.0 to cut atomics) ----
    unsigned floorb = 0x3F80u;
    for (int attempt = 0; attempt < 2; ++attempt) {
        hist[tid] = 0u;
        __syncthreads();
        for (int i = tid; i < NF / 8; i += 256) {
            const uint4 v = p4[i];
            const unsigned w[4] = {v.x, v.y, v.z, v.w};
#pragma unroll
            for (int q = 0; q < 4; ++q) {
                const unsigned k0 = w[q] & 0xFFFFu, k1 = w[q] >> 16;
                if (k0 > floorb) atomicAdd(&hist[k0 >> 8], 1u);
                if (k1 > floorb) atomicAdd(&hist[k1 >> 8], 1u);
            }
        }
        __syncthreads();
        if (tid == 0) {
            unsigned total = 0;
            for (int b = 0; b < 256; ++b) total += hist[b];
            if (total < NC) {
                if (attempt == 0) s_flag = 1u;
                else { s_flag = 2u; s_prefix = 0u; s_need = NC - total; }  // zerocase
            } else {
                unsigned cum = 0; int sel = 255;
                for (int b = 255; b >= 0; --b) {
                    const unsigned h = hist[b];
                    if (cum + h >= NC) { sel = b; break; }
                    cum += h;
                }
                s_flag = 0u; s_prefix = (unsigned)sel; s_need = NC - cum;
            }
        }
        __syncthreads();
        const unsigned flag = s_flag;
        selhi = s_prefix; need = s_need;
        __syncthreads();
        if (flag == 0u) break;
        if (flag == 2u) { fallback_scan = true; prefix = 0u; break; }
        floorb = 0u;
    }

    if (!fallback_scan) {
        // ---- fused pass 1: low-byte hist + compaction in ONE global read ----
        hist[tid] = 0u;
        if (tid == 0) { s_cnt = 0u; s_eqcnt = 0u; }
        __syncthreads();
        for (int i = tid; i < NF / 8; i += 256) {
            const uint4 v = p4[i];
            const unsigned w[4] = {v.x, v.y, v.z, v.w};
#pragma unroll
            for (int q = 0; q < 4; ++q) {
#pragma unroll
                for (int h = 0; h < 2; ++h) {
                    const unsigned k = h ? (w[q] >> 16) : (w[q] & 0xFFFFu);
                    const unsigned hi = k >> 8;
                    if (hi > selhi) {
                        const unsigned p = atomicAdd(&s_cnt, 1u);
                        if (p < NC) cand[p] = i * 8 + q * 2 + h;
                    } else if (hi == selhi) {
                        atomicAdd(&hist[k & 255u], 1u);
                        const unsigned e = atomicAdd(&s_eqcnt, 1u);
                        if (e < EQCAP)
                            eqbuf[e] = (k << 16) | (unsigned)(i * 8 + q * 2 + h);
                    }
                }
            }
        }
        __syncthreads();
        if (tid == 0) {
            unsigned cum = 0; int sel = 0;
            for (int b = 255; b >= 0; --b) {
                const unsigned h = hist[b];
                if (cum + h >= need) { sel = b; break; }
                cum += h;
            }
            s_prefix = (selhi << 8) | (unsigned)sel;
            s_need = need - cum;
            s_tiecnt = 0u;
        }
        __syncthreads();
        prefix = s_prefix; need = s_need;
        const unsigned eqtotal = s_eqcnt;
        __syncthreads();

        if (eqtotal <= EQCAP) {
            // in-smem final selection over the eq bucket
            for (unsigned e = tid; e < eqtotal; e += 256) {
                const unsigned ent = eqbuf[e];
                const unsigned k = ent >> 16;
                const int idx = (int)(ent & 0xFFFFu);
                if (k > prefix) {
                    const unsigned p = atomicAdd(&s_cnt, 1u);
                    if (p < NC) cand[p] = idx;
                } else if (k == prefix) {
                    const unsigned t = atomicAdd(&s_tiecnt, 1u);
                    if (t < 256u) tiebuf[t] = idx;
                }
            }
            __syncthreads();
            if (tid == 0) {
                const int g = (int)s_cnt;            // == NC - need
                const int m = (int)(s_tiecnt < 256u ? s_tiecnt : 256u);
                const int take = (int)need;
                for (int i = 0; i < take; ++i) {
                    if (i < m) {
                        int best = i;
                        for (int a = i + 1; a < m; ++a)
                            if (tiebuf[a] < tiebuf[best]) best = a;
                        const int t = tiebuf[i]; tiebuf[i] = tiebuf[best]; tiebuf[best] = t;
                        if (g + i < NC) cand[g + i] = tiebuf[i];
                    } else {
                        if (g + i < NC) cand[g + i] = NF - 1 - i;
                    }
                }
            }
            __syncthreads();
            if (tid < NC) g_cand[row * NC + tid] = cand[tid];
            return;
        }
        fallback_scan = true;   // eq bucket overflowed: correct slow path below
    }

    // ---- fallback: full global re-scan against 16-bit prefix ----
    if (tid == 0) { s_cnt = 0u; s_eqcnt = 0u; }
    __syncthreads();
    for (int i = tid; i < NF / 8; i += 256) {
        const uint4 v = p4[i];
        const unsigned w[4] = {v.x, v.y, v.z, v.w};
#pragma unroll
        for (int q = 0; q < 4; ++q) {
#pragma unroll
            for (int h = 0; h < 2; ++h) {
                const unsigned k = h ? (w[q] >> 16) : (w[q] & 0xFFFFu);
                const int j = i * 8 + q * 2 + h;
                if (k > prefix) {
                    const unsigned p = atomicAdd(&s_cnt, 1u);
                    if (p < NC) cand[p] = j;
                } else if (k == prefix) {
                    const unsigned e = atomicAdd(&s_eqcnt, 1u);
                    if (e < 256u) tiebuf[e] = j;
                }
            }
        }
    }
    __syncthreads();
    if (tid == 0) {
        const int g = (int)s_cnt;
        const int m = (int)(s_eqcnt < 256u ? s_eqcnt : 256u);
        const int take = (int)need;
        for (int i = 0; i < take; ++i) {
            if (i < m) {
                int best = i;
                for (int a = i + 1; a < m; ++a)
                    if (tiebuf[a] < tiebuf[best]) best = a;
                const int t = tiebuf[i]; tiebuf[i] = tiebuf[best]; tiebuf[best] = t;
                if (g + i < NC) cand[g + i] = tiebuf[i];
            } else {
                if (g + i < NC) cand[g + i] = NF - 1 - i;
            }
        }
    }
    __syncthreads();
    if (tid < NC) g_cand[row * NC + tid] = cand[tid];
}

// ================= exact refinement (Neumaier, unchanged math) ==============
__device__ __forceinline__ void neum(float& s, float& c, float& e, float a, float b) {
    const float p = a * b;
    e += fmaf(a, b, -p);
    const float t = s + p;
    c += (fabsf(s) >= fabsf(p)) ? ((s - t) + p) : ((p - t) + s);
    s = t;
}

__global__ void __launch_bounds__(512) refine_kernel(
    const float* __restrict__ X, const float* __restrict__ W,
    const float* __restrict__ benc, const float* __restrict__ bdec)
{
    const int row = blockIdx.x;
    const int tid = threadIdx.x;
    const int warp = tid >> 5;
    const int lane = tid & 31;

    __shared__ float  xs[ND];
    __shared__ double dv[NC];
    __shared__ int    di[NC];

    for (int j = tid; j < ND; j += 512)
        xs[j] = X[(size_t)row * ND + j] - bdec[j];
    if (tid < NC) di[tid] = g_cand[row * NC + tid];
    __syncthreads();

    for (int sweep = 0; sweep < 4; ++sweep) {
        const int c0 = sweep * 32 + warp * 2;
        const int f0 = di[c0], f1 = di[c0 + 1];
        const float4* __restrict__ w0 = (const float4*)(W + (size_t)f0 * ND);
        const float4* __restrict__ w1 = (const float4*)(W + (size_t)f1 * ND);
        float s0 = 0.f, cc0 = 0.f, e0 = 0.f;
        float s1 = 0.f, cc1 = 0.f, e1 = 0.f;
#pragma unroll
        for (int t = 0; t < 8; ++t) {
            const int j4 = t * 32 + lane;
            const float4 xv = *(const float4*)&xs[j4 * 4];
            const float4 a = __ldg(w0 + j4);
            const float4 b = __ldg(w1 + j4);
            neum(s0, cc0, e0, xv.x, a.x); neum(s1, cc1, e1, xv.x, b.x);
            neum(s0, cc0, e0, xv.y, a.y); neum(s1, cc1, e1, xv.y, b.y);
            neum(s0, cc0, e0, xv.z, a.z); neum(s1, cc1, e1, xv.z, b.z);
            neum(s0, cc0, e0, xv.w, a.w); neum(s1, cc1, e1, xv.w, b.w);
        }
        double t0 = (double)s0 + (double)cc0 + (double)e0;
        double t1 = (double)s1 + (double)cc1 + (double)e1;
#pragma unroll
        for (int m = 16; m > 0; m >>= 1) {
            t0 += __shfl_xor_sync(0xffffffffu, t0, m);
            t1 += __shfl_xor_sync(0xffffffffu, t1, m);
        }
        if (lane == 0) {
            t0 += (double)benc[f0];
            t1 += (double)benc[f1];
            dv[c0]     = t0 > 0.0 ? t0 : 0.0;
            dv[c0 + 1] = t1 > 0.0 ? t1 : 0.0;
        }
    }
    __syncthreads();

    if (tid < NC) {
        const double v = dv[tid];
        const int   ix = di[tid];
        int rank = 0;
#pragma unroll 8
        for (int j = 0; j < NC; ++j) {
            const double vj = dv[j];
            const int    ij = di[j];
            rank += (vj > v) || (vj == v && ij < ix);
        }
        if (rank < SELK) {
            g_vals[row * SELK + rank] = (float)v;
            g_idx [row * SELK + rank] = ix;
        }
    }
}

// =============================== decode =====================================
__global__ void __launch_bounds__(256) decode_kernel(const float* __restrict__ bdec,
                                                     float* __restrict__ out) {
    const int row = blockIdx.x;
    __shared__ float sv[SELK];
    __shared__ int   si[SELK];
    if (threadIdx.x < SELK) {
        sv[threadIdx.x] = g_vals[row * SELK + threadIdx.x];
        si[threadIdx.x] = g_idx [row * SELK + threadIdx.x];
    }
    __syncthreads();
    const int d = threadIdx.x * 4;
    float4 acc = *(const float4*)(bdec + d);
#pragma unroll 8
    for (int k = 0; k < SELK; ++k) {
        const float v = sv[k];
        const float4 w = *(const float4*)(g_wdect + (size_t)si[k] * ND + d);
        acc.x = fmaf(v, w.x, acc.x);
        acc.y = fmaf(v, w.y, acc.y);
        acc.z = fmaf(v, w.z, acc.z);
        acc.w = fmaf(v, w.w, acc.w);
    }
    *(float4*)(out + (size_t)row * ND + d) = acc;
}

// ============================================================================
extern "C" void kernel_launch(void* const* d_in, const int* in_sizes, int n_in,
                              void* d_out, int out_size) {
    const float* x    = (const float*)d_in[0];   // [4096, 1024]
    const float* Wenc = (const float*)d_in[1];   // [32768, 1024]
    const float* benc = (const float*)d_in[2];   // [32768]
    const float* Wdec = (const float*)d_in[3];   // [1024, 32768]
    const float* bdec = (const float*)d_in[4];   // [1024]
    float* out = (float*)d_out;                  // [4096, 1024]

    cudaFuncSetAttribute(gemm_bf16_kernel,
                         cudaFuncAttributeMaxDynamicSharedMemorySize, GEMM_SMEM);

    convx_kernel<<<256, 256>>>(x, bdec);
    convw_kernel<<<1024, 256>>>(Wenc);
    transpose_kernel<<<dim3(NF / 32, ND / 32), dim3(32, 8)>>>(Wdec);
    gemm_bf16_kernel<<<dim3(NF / GBN, NB / GBM), 256, GEMM_SMEM>>>(benc);
    topk_kernel<<<NB, 256>>>();
    refine_kernel<<<NB, 512>>>(x, Wenc, benc, bdec);
    decode_kernel<<<NB, 256>>>(bdec, out);
}

// round 6
// speedup vs baseline: 4.3284x; 1.0137x over previous
#include <cuda_runtime.h>
#include <cuda_bf16.h>
#include <stdint.h>

#define NB 4096
#define ND 1024
#define NF 32768
#define NC 128     // candidates kept per row
#define SELK 64    // exact top-k

// ---- GEMM tiling (HMMA mma.sync path; compute_103-safe) ----
#define GBM 128
#define GBN 128
#define GBK 64
#define KITERS (ND / GBK)          // 16
#define NSTAGE 3
#define OFF_A(s)  ((s) * 16384)              // A stages: 3 x 16KB
#define OFF_B(s)  (49152 + (s) * 16384)      // B stages: 3 x 16KB
#define OFF_BIAS  98304                      // 128 floats
#define GEMM_SMEM 98816
#define EPI_STRIDE 68              // u32 stride, conflict-free epilogue staging

// ---- device scratch (allocation-free) ----
static __device__ __align__(16) __nv_bfloat16 g_abf[(size_t)NB * ND];
static __device__ __align__(16) __nv_bfloat16 g_wbf[(size_t)NF * ND];
static __device__ __align__(16) __nv_bfloat16 g_prebf[(size_t)NB * NF];
static __device__ float g_wdect[(size_t)NF * ND];
static __device__ int   g_cand[NB * NC];
static __device__ float g_vals[NB * SELK];
static __device__ int   g_idx[NB * SELK];

// ============================ PTX helpers ===================================
__device__ __forceinline__ uint32_t smem_u32(const void* p) {
    uint32_t a;
    asm("{ .reg .u64 t; cvta.to.shared.u64 t, %1; cvt.u32.u64 %0, t; }"
        : "=r"(a) : "l"(p));
    return a;
}
__device__ __forceinline__ uint32_t pack_bf16x2(float lo, float hi) {
    uint32_t r;
    asm("cvt.rn.bf16x2.f32 %0, %2, %1;" : "=r"(r) : "f"(lo), "f"(hi));
    return r;
}
__device__ __forceinline__ void cp_async16(uint32_t dst, const void* src) {
    asm volatile("cp.async.cg.shared.global [%0], [%1], 16;"
                 :: "r"(dst), "l"(src) : "memory");
}
__device__ __forceinline__ void cp_commit() {
    asm volatile("cp.async.commit_group;" ::: "memory");
}
template <int N>
__device__ __forceinline__ void cp_wait() {
    asm volatile("cp.async.wait_group %0;" :: "n"(N) : "memory");
}
__device__ __forceinline__ void ldmatrix_x4(uint32_t& r0, uint32_t& r1,
                                            uint32_t& r2, uint32_t& r3, uint32_t a) {
    asm volatile("ldmatrix.sync.aligned.m8n8.x4.shared.b16 {%0,%1,%2,%3}, [%4];"
                 : "=r"(r0), "=r"(r1), "=r"(r2), "=r"(r3) : "r"(a));
}
__device__ __forceinline__ void mma_bf16(float* c, const uint32_t* a, const uint32_t* b) {
    asm volatile(
        "mma.sync.aligned.m16n8k16.row.col.f32.bf16.bf16.f32 "
        "{%0,%1,%2,%3}, {%4,%5,%6,%7}, {%8,%9}, {%0,%1,%2,%3};"
        : "+f"(c[0]), "+f"(c[1]), "+f"(c[2]), "+f"(c[3])
        : "r"(a[0]), "r"(a[1]), "r"(a[2]), "r"(a[3]), "r"(b[0]), "r"(b[1]));
}

// ======================== conversion kernels ================================
__global__ void __launch_bounds__(256) convx_kernel(const float* __restrict__ X,
                                                    const float* __restrict__ bdec) {
    const int n4 = NB * ND / 4;
    for (int i = blockIdx.x * 256 + threadIdx.x; i < n4; i += gridDim.x * 256) {
        const float4 v = ((const float4*)X)[i];
        const float4 bd = ((const float4*)bdec)[i & (ND / 4 - 1)];
        uint2 o;
        o.x = pack_bf16x2(v.x - bd.x, v.y - bd.y);
        o.y = pack_bf16x2(v.z - bd.z, v.w - bd.w);
        ((uint2*)g_abf)[i] = o;
    }
}
__global__ void __launch_bounds__(256) convw_kernel(const float* __restrict__ W) {
    const int n4 = NF * ND / 4;
    for (int i = blockIdx.x * 256 + threadIdx.x; i < n4; i += gridDim.x * 256) {
        const float4 v = ((const float4*)W)[i];
        uint2 o;
        o.x = pack_bf16x2(v.x, v.y);
        o.y = pack_bf16x2(v.z, v.w);
        ((uint2*)g_wbf)[i] = o;
    }
}

// ========================= W_dec transpose ==================================
__global__ void __launch_bounds__(256) transpose_kernel(const float* __restrict__ Wdec) {
    __shared__ float tile[32][33];
    const int f0 = blockIdx.x * 32;
    const int d0 = blockIdx.y * 32;
    const int tx = threadIdx.x, ty = threadIdx.y;
#pragma unroll
    for (int i = 0; i < 32; i += 8)
        tile[ty + i][tx] = Wdec[(size_t)(d0 + ty + i) * NF + (f0 + tx)];
    __syncthreads();
#pragma unroll
    for (int i = 0; i < 32; i += 8)
        g_wdect[(size_t)(f0 + ty + i) * ND + (d0 + tx)] = tile[tx][ty + i];
}

// ================ bf16 HMMA fast-score GEMM (3-stage cp.async) ==============
// smem rows are 128B (64 bf16); 16B chunk c of row r stored at chunk c^(r&7).
__device__ __forceinline__ uint32_t swz(uint32_t base, int row, int c) {
    return base + row * 128 + 16 * (c ^ (row & 7));
}

__global__ void __launch_bounds__(256, 2) gemm_bf16_kernel(const float* __restrict__ benc) {
    extern __shared__ char smem[];
    const uint32_t sbase = smem_u32(smem);
    const int tid = threadIdx.x;
    const int wid = tid >> 5;
    const int lane = tid & 31;
    const int warp_m = wid & 1;    // 2 warps over M (64 rows each)
    const int warp_n = wid >> 1;   // 4 warps over N (32 cols each)
    const int fcol = blockIdx.x * GBN;
    const int brow = blockIdx.y * GBM;

    float* sbias = (float*)(smem + OFF_BIAS);
    for (int i = tid; i < GBN; i += 256) sbias[i] = benc[fcol + i];

    const __nv_bfloat16* __restrict__ Ag = g_abf + (size_t)brow * ND;
    const __nv_bfloat16* __restrict__ Bg = g_wbf + (size_t)fcol * ND;

    const int lrow = tid >> 3;         // 0..31  (+32 per slot)
    const int lc = tid & 7;            // chunk 0..7

    // precomputed fragment row/chunk-phase (constant across iterations)
    const int arow_base = warp_m * 64 + (lane & 15);
    const int a_cphase  = lane >> 4;
    const int brow0 = warp_n * 32 + (lane & 7) + ((lane >> 4) << 3);
    const int b_cphase  = (lane >> 3) & 1;

    // prefetch stages 0 and 1
#pragma unroll
    for (int st = 0; st < 2; ++st) {
        const int kb = st * GBK;
#pragma unroll
        for (int s = 0; s < 4; ++s) {
            const int row = lrow + s * 32;
            cp_async16(swz(sbase + OFF_A(st), row, lc), Ag + (size_t)row * ND + kb + lc * 8);
            cp_async16(swz(sbase + OFF_B(st), row, lc), Bg + (size_t)row * ND + kb + lc * 8);
        }
        cp_commit();
    }

    float acc[4][4][4];
#pragma unroll
    for (int i = 0; i < 4; ++i)
#pragma unroll
        for (int j = 0; j < 4; ++j)
#pragma unroll
            for (int r = 0; r < 4; ++r) acc[i][j][r] = 0.f;

    uint32_t af[2][4][4], bfr[2][2][4];

    for (int it = 0; it < KITERS; ++it) {
        const int buf = it % NSTAGE;
        cp_wait<1>();          // stage `it` resident (1 younger group in flight)
        __syncthreads();       // compute of it-1 finished everywhere

        // issue stage it+2 into buffer (it+2)%3
        if (it + 2 < KITERS) {
            const int kb = (it + 2) * GBK;
            const int nbuf = (it + 2) % NSTAGE;
#pragma unroll
            for (int s = 0; s < 4; ++s) {
                const int row = lrow + s * 32;
                cp_async16(swz(sbase + OFF_A(nbuf), row, lc), Ag + (size_t)row * ND + kb + lc * 8);
                cp_async16(swz(sbase + OFF_B(nbuf), row, lc), Bg + (size_t)row * ND + kb + lc * 8);
            }
        }
        cp_commit();

        const uint32_t sA = sbase + OFF_A(buf);
        const uint32_t sB = sbase + OFF_B(buf);

        // load ks=0 fragments
#pragma unroll
        for (int i = 0; i < 4; ++i)
            ldmatrix_x4(af[0][i][0], af[0][i][1], af[0][i][2], af[0][i][3],
                        swz(sA, arow_base + i * 16, a_cphase));
#pragma unroll
        for (int j2 = 0; j2 < 2; ++j2)
            ldmatrix_x4(bfr[0][j2][0], bfr[0][j2][1], bfr[0][j2][2], bfr[0][j2][3],
                        swz(sB, brow0 + j2 * 16, b_cphase));

#pragma unroll
        for (int ks = 0; ks < 4; ++ks) {
            const int cur = ks & 1, nxt = cur ^ 1;
            if (ks < 3) {
                const int c0 = (ks + 1) * 2;
#pragma unroll
                for (int i = 0; i < 4; ++i)
                    ldmatrix_x4(af[nxt][i][0], af[nxt][i][1], af[nxt][i][2], af[nxt][i][3],
                                swz(sA, arow_base + i * 16, c0 + a_cphase));
#pragma unroll
                for (int j2 = 0; j2 < 2; ++j2)
                    ldmatrix_x4(bfr[nxt][j2][0], bfr[nxt][j2][1], bfr[nxt][j2][2], bfr[nxt][j2][3],
                                swz(sB, brow0 + j2 * 16, c0 + b_cphase));
            }
#pragma unroll
            for (int i = 0; i < 4; ++i)
#pragma unroll
                for (int j = 0; j < 4; ++j)
                    mma_bf16(acc[i][j], af[cur][i], &bfr[cur][j >> 1][(j & 1) * 2]);
        }
    }
    __syncthreads();

    // epilogue: +bias, relu, bf16 pack -> staged smem -> coalesced gmem
    uint32_t* epi = (uint32_t*)smem;
    const int g = lane >> 2, tig = lane & 3;
#pragma unroll
    for (int i = 0; i < 4; ++i) {
#pragma unroll
        for (int j = 0; j < 4; ++j) {
            const int col = warp_n * 32 + j * 8 + 2 * tig;
            const float b0 = sbias[col], b1 = sbias[col + 1];
            const int cp = col >> 1;
            float v0 = acc[i][j][0] + b0, v1 = acc[i][j][1] + b1;
            float v2 = acc[i][j][2] + b0, v3 = acc[i][j][3] + b1;
            v0 = v0 > 0.f ? v0 : 0.f; v1 = v1 > 0.f ? v1 : 0.f;
            v2 = v2 > 0.f ? v2 : 0.f; v3 = v3 > 0.f ? v3 : 0.f;
            const int row0 = warp_m * 64 + i * 16 + g;
            epi[(row0)     * EPI_STRIDE + cp] = pack_bf16x2(v0, v1);
            epi[(row0 + 8) * EPI_STRIDE + cp] = pack_bf16x2(v2, v3);
        }
    }
    __syncthreads();
#pragma unroll
    for (int s = 0; s < 8; ++s) {
        const int idx = tid + s * 256;          // 0..2047
        const int row = idx >> 4, q = idx & 15;
        uint4 v;
        v.x = epi[row * EPI_STRIDE + q * 4 + 0];
        v.y = epi[row * EPI_STRIDE + q * 4 + 1];
        v.z = epi[row * EPI_STRIDE + q * 4 + 2];
        v.w = epi[row * EPI_STRIDE + q * 4 + 3];
        *(uint4*)(g_prebf + (size_t)(brow + row) * NF + fcol + q * 8) = v;
    }
}

// ====== per-row top-NC candidates: single-pass threshold collection =========
#define T0KEY 0x3FE0u   // bf16(1.75): rank-128 threshold ~2.66 >> 1.75
#define CAP 4096

__global__ void __launch_bounds__(256) topk_kernel() {
    const int row = blockIdx.x;
    const uint4* __restrict__ p4 = (const uint4*)(g_prebf + (size_t)row * NF);
    const int tid = threadIdx.x;

    __shared__ unsigned buf[CAP];       // (key16 << 16) | idx
    __shared__ unsigned hist[256];
    __shared__ unsigned s_n, s_prefix, s_need, s_flag, s_cnt, s_tiecnt;
    __shared__ int cand[NC];
    __shared__ int tiebuf[256];

    if (tid == 0) s_n = 0u;
    __syncthreads();

    // ---- single global sweep: collect all values > 1.75 ----
    for (int i = tid; i < NF / 8; i += 256) {
        const uint4 v = p4[i];
        const unsigned w[4] = {v.x, v.y, v.z, v.w};
#pragma unroll
        for (int q = 0; q < 4; ++q) {
            const unsigned k0 = w[q] & 0xFFFFu, k1 = w[q] >> 16;
            if (k0 > T0KEY) {
                const unsigned p = atomicAdd(&s_n, 1u);
                if (p < CAP) buf[p] = (k0 << 16) | (unsigned)(i * 8 + q * 2);
            }
            if (k1 > T0KEY) {
                const unsigned p = atomicAdd(&s_n, 1u);
                if (p < CAP) buf[p] = (k1 << 16) | (unsigned)(i * 8 + q * 2 + 1);
            }
        }
    }
    __syncthreads();
    const unsigned n = s_n;

    if (n >= NC && n <= CAP) {
        // ---------- in-smem 2-level radix select over n entries ----------
        hist[tid] = 0u;
        __syncthreads();
        for (unsigned e = tid; e < n; e += 256)
            atomicAdd(&hist[buf[e] >> 24], 1u);
        __syncthreads();
        if (tid == 0) {
            unsigned cum = 0; int sel = 255;
            for (int b = 255; b >= 0; --b) {
                const unsigned h = hist[b];
                if (cum + h >= NC) { sel = b; break; }
                cum += h;
            }
            s_prefix = (unsigned)sel;
            s_need = NC - cum;
        }
        __syncthreads();
        const unsigned selhi = s_prefix;
        unsigned need = s_need;
        __syncthreads();

        hist[tid] = 0u;
        __syncthreads();
        for (unsigned e = tid; e < n; e += 256) {
            const unsigned k = buf[e] >> 16;
            if ((k >> 8) == selhi) atomicAdd(&hist[k & 255u], 1u);
        }
        __syncthreads();
        if (tid == 0) {
            unsigned cum = 0; int sel = 0;
            for (int b = 255; b >= 0; --b) {
                const unsigned h = hist[b];
                if (cum + h >= need) { sel = b; break; }
                cum += h;
            }
            s_prefix = (selhi << 8) | (unsigned)sel;
            s_need = need - cum;
            s_cnt = 0u; s_tiecnt = 0u;
        }
        __syncthreads();
        const unsigned prefix = s_prefix;
        need = s_need;
        __syncthreads();

        for (unsigned e = tid; e < n; e += 256) {
            const unsigned k = buf[e] >> 16;
            const int idx = (int)(buf[e] & 0xFFFFu);
            if (k > prefix) {
                const unsigned p = atomicAdd(&s_cnt, 1u);
                if (p < NC) cand[p] = idx;
            } else if (k == prefix) {
                const unsigned t = atomicAdd(&s_tiecnt, 1u);
                if (t < 256u) tiebuf[t] = idx;
            }
        }
        __syncthreads();
        if (tid == 0) {
            const int g = (int)s_cnt;            // == NC - need
            const int m = (int)(s_tiecnt < 256u ? s_tiecnt : 256u);
            const int take = (int)need;
            for (int i = 0; i < take; ++i) {
                if (i < m) {
                    int best = i;
                    for (int a = i + 1; a < m; ++a)
                        if (tiebuf[a] < tiebuf[best]) best = a;
                    const int t = tiebuf[i]; tiebuf[i] = tiebuf[best]; tiebuf[best] = t;
                    if (g + i < NC) cand[g + i] = tiebuf[i];
                } else {
                    if (g + i < NC) cand[g + i] = NF - 1 - i;
                }
            }
        }
        __syncthreads();
        if (tid < NC) g_cand[row * NC + tid] = cand[tid];
        return;
    }

    // ---------------- fallback: full 2-pass global radix -------------------
    unsigned selhi = 0, need = NC, prefix = 0;
    bool zerocase = false;
    hist[tid] = 0u;
    __syncthreads();
    for (int i = tid; i < NF / 8; i += 256) {
        const uint4 v = p4[i];
        const unsigned w[4] = {v.x, v.y, v.z, v.w};
#pragma unroll
        for (int q = 0; q < 4; ++q) {
            const unsigned k0 = w[q] & 0xFFFFu, k1 = w[q] >> 16;
            if (k0 > 0u) atomicAdd(&hist[k0 >> 8], 1u);
            if (k1 > 0u) atomicAdd(&hist[k1 >> 8], 1u);
        }
    }
    __syncthreads();
    if (tid == 0) {
        unsigned total = 0;
        for (int b = 0; b < 256; ++b) total += hist[b];
        if (total < NC) { s_flag = 2u; s_prefix = 0u; s_need = NC - total; }
        else {
            unsigned cum = 0; int sel = 255;
            for (int b = 255; b >= 0; --b) {
                const unsigned h = hist[b];
                if (cum + h >= NC) { sel = b; break; }
                cum += h;
            }
            s_flag = 0u; s_prefix = (unsigned)sel; s_need = NC - cum;
        }
    }
    __syncthreads();
    {
        const unsigned flag = s_flag;
        selhi = s_prefix; need = s_need;
        __syncthreads();
        if (flag == 2u) { zerocase = true; prefix = 0u; }
    }

    if (!zerocase) {
        hist[tid] = 0u;
        __syncthreads();
        for (int i = tid; i < NF / 8; i += 256) {
            const uint4 v = p4[i];
            const unsigned w[4] = {v.x, v.y, v.z, v.w};
#pragma unroll
            for (int q = 0; q < 4; ++q) {
                const unsigned k0 = w[q] & 0xFFFFu, k1 = w[q] >> 16;
                if ((k0 >> 8) == selhi) atomicAdd(&hist[k0 & 255u], 1u);
                if ((k1 >> 8) == selhi) atomicAdd(&hist[k1 & 255u], 1u);
            }
        }
        __syncthreads();
        if (tid == 0) {
            unsigned cum = 0; int sel = 0;
            for (int b = 255; b >= 0; --b) {
                const unsigned h = hist[b];
                if (cum + h >= need) { sel = b; break; }
                cum += h;
            }
            s_prefix = (selhi << 8) | (unsigned)sel;
            s_need = need - cum;
        }
        __syncthreads();
        prefix = s_prefix; need = s_need;
        __syncthreads();
    }

    if (tid == 0) { s_cnt = 0u; s_tiecnt = 0u; }
    __syncthreads();
    for (int i = tid; i < NF / 8; i += 256) {
        const uint4 v = p4[i];
        const unsigned w[4] = {v.x, v.y, v.z, v.w};
#pragma unroll
        for (int q = 0; q < 4; ++q) {
#pragma unroll
            for (int h = 0; h < 2; ++h) {
                const unsigned k = h ? (w[q] >> 16) : (w[q] & 0xFFFFu);
                const int j = i * 8 + q * 2 + h;
                if (k > prefix) {
                    const unsigned p = atomicAdd(&s_cnt, 1u);
                    if (p < NC) cand[p] = j;
                } else if (k == prefix) {
                    const unsigned e = atomicAdd(&s_tiecnt, 1u);
                    if (e < 256u) tiebuf[e] = j;
                }
            }
        }
    }
    __syncthreads();
    if (tid == 0) {
        const int g = (int)s_cnt;
        const int m = (int)(s_tiecnt < 256u ? s_tiecnt : 256u);
        const int take = (int)need;
        for (int i = 0; i < take; ++i) {
            if (i < m) {
                int best = i;
                for (int a = i + 1; a < m; ++a)
                    if (tiebuf[a] < tiebuf[best]) best = a;
                const int t = tiebuf[i]; tiebuf[i] = tiebuf[best]; tiebuf[best] = t;
                if (g + i < NC) cand[g + i] = tiebuf[i];
            } else {
                if (g + i < NC) cand[g + i] = NF - 1 - i;
            }
        }
    }
    __syncthreads();
    if (tid < NC) g_cand[row * NC + tid] = cand[tid];
}

// ================= exact refinement (Neumaier, unchanged math) ==============
__device__ __forceinline__ void neum(float& s, float& c, float& e, float a, float b) {
    const float p = a * b;
    e += fmaf(a, b, -p);
    const float t = s + p;
    c += (fabsf(s) >= fabsf(p)) ? ((s - t) + p) : ((p - t) + s);
    s = t;
}

__global__ void __launch_bounds__(512) refine_kernel(
    const float* __restrict__ X, const float* __restrict__ W,
    const float* __restrict__ benc, const float* __restrict__ bdec)
{
    const int row = blockIdx.x;
    const int tid = threadIdx.x;
    const int warp = tid >> 5;
    const int lane = tid & 31;

    __shared__ float  xs[ND];
    __shared__ double dv[NC];
    __shared__ int    di[NC];

    for (int j = tid; j < ND; j += 512)
        xs[j] = X[(size_t)row * ND + j] - bdec[j];
    if (tid < NC) di[tid] = g_cand[row * NC + tid];
    __syncthreads();

    for (int sweep = 0; sweep < 4; ++sweep) {
        const int c0 = sweep * 32 + warp * 2;
        const int f0 = di[c0], f1 = di[c0 + 1];
        const float4* __restrict__ w0 = (const float4*)(W + (size_t)f0 * ND);
        const float4* __restrict__ w1 = (const float4*)(W + (size_t)f1 * ND);
        float s0 = 0.f, cc0 = 0.f, e0 = 0.f;
        float s1 = 0.f, cc1 = 0.f, e1 = 0.f;
#pragma unroll
        for (int t = 0; t < 8; ++t) {
            const int j4 = t * 32 + lane;
            const float4 xv = *(const float4*)&xs[j4 * 4];
            const float4 a = __ldg(w0 + j4);
            const float4 b = __ldg(w1 + j4);
            neum(s0, cc0, e0, xv.x, a.x); neum(s1, cc1, e1, xv.x, b.x);
            neum(s0, cc0, e0, xv.y, a.y); neum(s1, cc1, e1, xv.y, b.y);
            neum(s0, cc0, e0, xv.z, a.z); neum(s1, cc1, e1, xv.z, b.z);
            neum(s0, cc0, e0, xv.w, a.w); neum(s1, cc1, e1, xv.w, b.w);
        }
        double t0 = (double)s0 + (double)cc0 + (double)e0;
        double t1 = (double)s1 + (double)cc1 + (double)e1;
#pragma unroll
        for (int m = 16; m > 0; m >>= 1) {
            t0 += __shfl_xor_sync(0xffffffffu, t0, m);
            t1 += __shfl_xor_sync(0xffffffffu, t1, m);
        }
        if (lane == 0) {
            t0 += (double)benc[f0];
            t1 += (double)benc[f1];
            dv[c0]     = t0 > 0.0 ? t0 : 0.0;
            dv[c0 + 1] = t1 > 0.0 ? t1 : 0.0;
        }
    }
    __syncthreads();

    if (tid < NC) {
        const double v = dv[tid];
        const int   ix = di[tid];
        int rank = 0;
#pragma unroll 8
        for (int j = 0; j < NC; ++j) {
            const double vj = dv[j];
            const int    ij = di[j];
            rank += (vj > v) || (vj == v && ij < ix);
        }
        if (rank < SELK) {
            g_vals[row * SELK + rank] = (float)v;
            g_idx [row * SELK + rank] = ix;
        }
    }
}

// =============================== decode =====================================
__global__ void __launch_bounds__(256) decode_kernel(const float* __restrict__ bdec,
                                                     float* __restrict__ out) {
    const int row = blockIdx.x;
    __shared__ float sv[SELK];
    __shared__ int   si[SELK];
    if (threadIdx.x < SELK) {
        sv[threadIdx.x] = g_vals[row * SELK + threadIdx.x];
        si[threadIdx.x] = g_idx [row * SELK + threadIdx.x];
    }
    __syncthreads();
    const int d = threadIdx.x * 4;
    float4 acc = *(const float4*)(bdec + d);
#pragma unroll 8
    for (int k = 0; k < SELK; ++k) {
        const float v = sv[k];
        const float4 w = *(const float4*)(g_wdect + (size_t)si[k] * ND + d);
        acc.x = fmaf(v, w.x, acc.x);
        acc.y = fmaf(v, w.y, acc.y);
        acc.z = fmaf(v, w.z, acc.z);
        acc.w = fmaf(v, w.w, acc.w);
    }
    *(float4*)(out + (size_t)row * ND + d) = acc;
}

// ============================================================================
extern "C" void kernel_launch(void* const* d_in, const int* in_sizes, int n_in,
                              void* d_out, int out_size) {
    const float* x    = (const float*)d_in[0];   // [4096, 1024]
    const float* Wenc = (const float*)d_in[1];   // [32768, 1024]
    const float* benc = (const float*)d_in[2];   // [32768]
    const float* Wdec = (const float*)d_in[3];   // [1024, 32768]
    const float* bdec = (const float*)d_in[4];   // [1024]
    float* out = (float*)d_out;                  // [4096, 1024]

    cudaFuncSetAttribute(gemm_bf16_kernel,
                         cudaFuncAttributeMaxDynamicSharedMemorySize, GEMM_SMEM);

    convx_kernel<<<256, 256>>>(x, bdec);
    convw_kernel<<<1024, 256>>>(Wenc);
    transpose_kernel<<<dim3(NF / 32, ND / 32), dim3(32, 8)>>>(Wdec);
    gemm_bf16_kernel<<<dim3(NF / GBN, NB / GBM), 256, GEMM_SMEM>>>(benc);
    topk_kernel<<<NB, 256>>>();
    refine_kernel<<<NB, 512>>>(x, Wenc, benc, bdec);
    decode_kernel<<<NB, 256>>>(bdec, out);
}